// round 4
// baseline (speedup 1.0000x reference)
#include <cuda_runtime.h>
#include <math.h>

#define HD 4096
#define LD 4096
#define VD 128000

// ---------------- scratch (device globals; no allocations) ----------------
__device__ __align__(16) float g_logits[LD];
__device__ float g_lse_attn;
__device__ __align__(16) float g_attn_applied[HD];
__device__ __align__(16) float g_lstm_in[HD];
__device__ __align__(16) float g_gates[4 * HD];
__device__ __align__(16) float g_hnew[HD];
__device__ __align__(16) float g_word[VD];
__device__ float g_pmax[VD / 256];
__device__ float g_psum[VD / 256];
__device__ float g_lse_word;

// ---------------- 8-deep front-batched dot over a row segment ----------------
// a, v are float4 bases; covers [i0, i0+n4) with n4 % 256 == 0.
// Returns per-lane partial (caller does the warp reduce).
__device__ __forceinline__ float dot_seg(const float4* __restrict__ a,
                                         const float4* __restrict__ v,
                                         int i0, int n4, int lane)
{
    float s = 0.0f;
    for (int base = i0 + lane; base < i0 + n4; base += 256) {
        float4 r[8];
        #pragma unroll
        for (int j = 0; j < 8; ++j) r[j] = a[base + j * 32];
        #pragma unroll
        for (int j = 0; j < 8; ++j) {
            float4 vv = v[base + j * 32];
            s += r[j].x * vv.x + r[j].y * vv.y + r[j].z * vv.z + r[j].w * vv.w;
        }
    }
    return s;
}

__device__ __forceinline__ float warp_sum(float s) {
    #pragma unroll
    for (int o = 16; o; o >>= 1) s += __shfl_xor_sync(0xFFFFFFFFu, s, o);
    return s;
}

// ---------------- K0: zero the atomically-accumulated scratch ----------------
__global__ void zero_kernel() {
    int i = blockIdx.x * blockDim.x + threadIdx.x;   // grid 16 x 256 = 4096
    g_logits[i] = 0.0f;
    g_lstm_in[i] = 0.0f;
    g_attn_applied[i] = 0.0f;
}

// ---------------- K1: attn logits (split S=2) + W_hh@h gates, one launch ----
// blocks [0, 1024): attn logits, warp = (row, seg)   rows=L, dual stream
// blocks [1024, 3072): hh gates, warp-per-row         rows=4H, single stream
#define NA_BLOCKS 1024
__global__ __launch_bounds__(256) void phase1_kernel(
    const float* __restrict__ W_attn, const float* __restrict__ b_attn,
    const float* __restrict__ h0, const float* __restrict__ x0,
    const float* __restrict__ W_hh, const float* __restrict__ b_hh)
{
    int wid = threadIdx.x >> 5, lane = threadIdx.x & 31;
    if (blockIdx.x < NA_BLOCKS) {
        int w = blockIdx.x * 8 + wid;
        int row = w >> 1, seg = w & 1;
        const float4* a = (const float4*)(W_attn + (size_t)row * 2 * HD);
        const float4* b = a + HD / 4;
        int i0 = seg * (HD / 8);   // 512 float4s per segment
        float s = dot_seg(a, (const float4*)h0, i0, HD / 8, lane)
                + dot_seg(b, (const float4*)x0, i0, HD / 8, lane);
        s = warp_sum(s);
        if (lane == 0)
            atomicAdd(&g_logits[row], s + (seg == 0 ? b_attn[row] : 0.0f));
    } else {
        int row = (blockIdx.x - NA_BLOCKS) * 8 + wid;   // [0, 4H)
        const float4* a = (const float4*)(W_hh + (size_t)row * HD);
        float s = dot_seg(a, (const float4*)h0, 0, HD / 4, lane);
        s = warp_sum(s);
        if (lane == 0) g_gates[row] = s + b_hh[row];    // sole writer; ih adds later
    }
}

// ---------------- block reduction helpers ----------------
__device__ __forceinline__ float block_reduce_max(float v, float* sm) {
    int lane = threadIdx.x & 31, wid = threadIdx.x >> 5;
    int nwarp = blockDim.x >> 5;
    #pragma unroll
    for (int o = 16; o; o >>= 1) v = fmaxf(v, __shfl_xor_sync(0xFFFFFFFFu, v, o));
    if (lane == 0) sm[wid] = v;
    __syncthreads();
    float r = (threadIdx.x < nwarp) ? sm[threadIdx.x] : -1e30f;
    if (wid == 0) {
        #pragma unroll
        for (int o = 16; o; o >>= 1) r = fmaxf(r, __shfl_xor_sync(0xFFFFFFFFu, r, o));
        if (lane == 0) sm[0] = r;
    }
    __syncthreads();
    float m = sm[0];
    __syncthreads();
    return m;
}

__device__ __forceinline__ float block_reduce_sum(float v, float* sm) {
    int lane = threadIdx.x & 31, wid = threadIdx.x >> 5;
    int nwarp = blockDim.x >> 5;
    #pragma unroll
    for (int o = 16; o; o >>= 1) v += __shfl_xor_sync(0xFFFFFFFFu, v, o);
    if (lane == 0) sm[wid] = v;
    __syncthreads();
    float r = (threadIdx.x < nwarp) ? sm[threadIdx.x] : 0.0f;
    if (wid == 0) {
        #pragma unroll
        for (int o = 16; o; o >>= 1) r += __shfl_xor_sync(0xFFFFFFFFu, r, o);
        if (lane == 0) sm[0] = r;
    }
    __syncthreads();
    float s = sm[0];
    __syncthreads();
    return s;
}

// ---------------- K2: attention logsumexp (L=4096, one block) ----------------
__global__ void attn_lse_kernel() {
    __shared__ float sm[32];
    int t = threadIdx.x;
    float m = -1e30f;
    for (int i = t; i < LD; i += blockDim.x) m = fmaxf(m, g_logits[i]);
    float M = block_reduce_max(m, sm);
    float s = 0.0f;
    for (int i = t; i < LD; i += blockDim.x) s += expf(g_logits[i] - M);
    float S = block_reduce_sum(s, sm);
    if (t == 0) g_lse_attn = M + logf(S);
}

// ---------------- K3: attn_applied[c] = sum_l (logit[l]-lse) * enc[l,c] -----
// grid (4, 64) x 256 threads; float4 columns, 64-row slices, atomicAdd.
__global__ void attn_applied_kernel(const float* __restrict__ enc) {
    int c4 = blockIdx.x * blockDim.x + threadIdx.x;   // float4 column index
    int l0 = blockIdx.y * (LD / 64);
    float lse = g_lse_attn;
    const float4* e = (const float4*)enc;
    float4 acc = make_float4(0.f, 0.f, 0.f, 0.f);
    #pragma unroll 4
    for (int l = l0; l < l0 + LD / 64; ++l) {
        float w = g_logits[l] - lse;
        float4 ev = e[(size_t)l * (HD / 4) + c4];
        acc.x += w * ev.x; acc.y += w * ev.y;
        acc.z += w * ev.z; acc.w += w * ev.w;
    }
    atomicAdd(&g_attn_applied[c4 * 4 + 0], acc.x);
    atomicAdd(&g_attn_applied[c4 * 4 + 1], acc.y);
    atomicAdd(&g_attn_applied[c4 * 4 + 2], acc.z);
    atomicAdd(&g_attn_applied[c4 * 4 + 3], acc.w);
}

// ---------------- K4: lstm_in = [x, attn_applied] @ W_comb^T + b  (S=2) ----
__global__ __launch_bounds__(256) void comb_kernel(
    const float* __restrict__ W_comb, const float* __restrict__ b_comb,
    const float* __restrict__ x0)
{
    int wid = threadIdx.x >> 5, lane = threadIdx.x & 31;
    int w = blockIdx.x * 8 + wid;          // grid 1024
    int row = w >> 1, seg = w & 1;
    const float4* a = (const float4*)(W_comb + (size_t)row * 2 * HD);
    const float4* b = a + HD / 4;
    int i0 = seg * (HD / 8);
    float s = dot_seg(a, (const float4*)x0, i0, HD / 8, lane)
            + dot_seg(b, (const float4*)g_attn_applied, i0, HD / 8, lane);
    s = warp_sum(s);
    if (lane == 0)
        atomicAdd(&g_lstm_in[row], s + (seg == 0 ? b_comb[row] : 0.0f));
}

// ---------------- K5: gates += W_ih @ lstm_in + b_ih ------------------------
__global__ __launch_bounds__(256) void ih_kernel(
    const float* __restrict__ W_ih, const float* __restrict__ b_ih)
{
    int wid = threadIdx.x >> 5, lane = threadIdx.x & 31;
    int row = blockIdx.x * 8 + wid;        // grid 2048 -> rows [0, 4H)
    const float4* a = (const float4*)(W_ih + (size_t)row * HD);
    float s = dot_seg(a, (const float4*)g_lstm_in, 0, HD / 4, lane);
    s = warp_sum(s);
    if (lane == 0) atomicAdd(&g_gates[row], s + b_ih[row]);
}

// ---------------- K6: LSTM cell elementwise ----------------
__global__ void lstm_kernel(const float* __restrict__ c0) {
    int i = blockIdx.x * blockDim.x + threadIdx.x;
    if (i >= HD) return;
    float ig = g_gates[i];
    float fg = g_gates[i + HD];
    float gg = g_gates[i + 2 * HD];
    float og = g_gates[i + 3 * HD];
    float si = 1.0f / (1.0f + expf(-ig));
    float sf = 1.0f / (1.0f + expf(-fg));
    float so = 1.0f / (1.0f + expf(-og));
    float cn = sf * c0[i] + si * tanhf(gg);
    g_hnew[i] = so * tanhf(cn);
}

// ---------------- K7: word = h_new @ W_out^T + b_out  (2.1 GB) --------------
__global__ __launch_bounds__(256) void wout_kernel(
    const float* __restrict__ W_out, const float* __restrict__ b_out)
{
    int wid = threadIdx.x >> 5, lane = threadIdx.x & 31;
    int row = blockIdx.x * 8 + wid;        // grid 16000
    const float4* a = (const float4*)(W_out + (size_t)row * HD);
    float s = dot_seg(a, (const float4*)g_hnew, 0, HD / 4, lane);
    s = warp_sum(s);
    if (lane == 0) g_word[row] = s + b_out[row];
}

// ---------------- K8: vocab logsumexp stage A ----------------
__global__ void word_lse_partial_kernel() {
    __shared__ float sm[32];
    int idx = blockIdx.x * blockDim.x + threadIdx.x;
    float x = g_word[idx];                 // V divisible by 256
    float M = block_reduce_max(x, sm);
    float S = block_reduce_sum(expf(x - M), sm);
    if (threadIdx.x == 0) { g_pmax[blockIdx.x] = M; g_psum[blockIdx.x] = S; }
}

// ---------------- K9: vocab logsumexp stage B ----------------
__global__ void word_lse_final_kernel(int nparts) {
    __shared__ float sm[32];
    int t = threadIdx.x;
    float m = (t < nparts) ? g_pmax[t] : -1e30f;
    float M = block_reduce_max(m, sm);
    float s = (t < nparts) ? g_psum[t] * expf(g_pmax[t] - M) : 0.0f;
    float S = block_reduce_sum(s, sm);
    if (t == 0) g_lse_word = M + logf(S);
}

// ---------------- K10: out = word - lse ----------------
__global__ void final_kernel(float* __restrict__ out) {
    int i = blockIdx.x * blockDim.x + threadIdx.x;
    if (i < VD) out[i] = g_word[i] - g_lse_word;
}

// ======================================================================
extern "C" void kernel_launch(void* const* d_in, const int* in_sizes, int n_in,
                              void* d_out, int out_size) {
    const float* enc    = (const float*)d_in[0];
    const float* h0     = (const float*)d_in[1];
    const float* c0     = (const float*)d_in[2];
    const float* x0     = (const float*)d_in[3];
    const float* W_attn = (const float*)d_in[4];
    const float* b_attn = (const float*)d_in[5];
    const float* W_comb = (const float*)d_in[6];
    const float* b_comb = (const float*)d_in[7];
    const float* W_ih   = (const float*)d_in[8];
    const float* b_ih   = (const float*)d_in[9];
    const float* W_hh   = (const float*)d_in[10];
    const float* b_hh   = (const float*)d_in[11];
    const float* W_out  = (const float*)d_in[12];
    const float* b_out  = (const float*)d_in[13];
    float* out = (float*)d_out;

    const int TPB = 256;

    // K0: zero atomically-accumulated scratch (logits, lstm_in, attn_applied)
    zero_kernel<<<HD / TPB, TPB>>>();
    // K1: attn logits (S=2, 1024 blocks) + W_hh@h gates (2048 blocks), fused
    phase1_kernel<<<NA_BLOCKS + (4 * HD) / 8, TPB>>>(W_attn, b_attn, h0, x0,
                                                     W_hh, b_hh);
    // K2: lse over L
    attn_lse_kernel<<<1, 1024>>>();
    // K3: attn_applied = (logits - lse) @ enc   (64 MB, 256 blocks)
    attn_applied_kernel<<<dim3(HD / 4 / TPB, 64), TPB>>>(enc);
    // K4: lstm_in = [x, attn_applied] @ W_comb^T + b   (S=2, 1024 blocks)
    comb_kernel<<<(2 * HD) / 8, TPB>>>(W_comb, b_comb, x0);
    // K5: gates += W_ih @ lstm_in + b_ih   (256 MB, 2048 blocks)
    ih_kernel<<<(4 * HD) / 8, TPB>>>(W_ih, b_ih);
    // K6: LSTM cell
    lstm_kernel<<<HD / TPB, TPB>>>(c0);
    // K7: word = h_new @ W_out^T + b_out   (2.1 GB, 16000 blocks)
    wout_kernel<<<VD / 8, TPB>>>(W_out, b_out);
    // K8-9: logsumexp over V
    word_lse_partial_kernel<<<VD / TPB, TPB>>>();
    word_lse_final_kernel<<<1, 512>>>(VD / TPB);
    // K10: out = word - lse
    final_kernel<<<VD / TPB, TPB>>>(out);
}

// round 5
// speedup vs baseline: 1.0083x; 1.0083x over previous
#include <cuda_runtime.h>
#include <math.h>

#define HD 4096
#define LD 4096
#define VD 128000

// ---------------- scratch (device globals; no allocations) ----------------
__device__ __align__(16) float g_log0[LD];         // attn logits partial seg0 (+bias)
__device__ __align__(16) float g_log1[LD];         // attn logits partial seg1
__device__ __align__(16) float g_attn_applied[HD]; // zeroed by phase1, atomics in K2
__device__ __align__(16) float g_lstm_in[HD];      // zeroed by phase1, atomics in K3
__device__ __align__(16) float g_gates[4 * HD];    // base by phase1, atomics in K4
__device__ __align__(16) float g_hnew[HD];
__device__ __align__(16) float g_word[VD];
__device__ float g_pmax[VD / 256];
__device__ float g_psum[VD / 256];
__device__ float g_lse_word;

// ---------------- 8-deep front-batched dot over a row segment ----------------
__device__ __forceinline__ float dot_seg(const float4* __restrict__ a,
                                         const float4* __restrict__ v,
                                         int i0, int n4, int lane)
{
    float s = 0.0f;
    for (int base = i0 + lane; base < i0 + n4; base += 256) {
        float4 r[8];
        #pragma unroll
        for (int j = 0; j < 8; ++j) r[j] = a[base + j * 32];
        #pragma unroll
        for (int j = 0; j < 8; ++j) {
            float4 vv = v[base + j * 32];
            s += r[j].x * vv.x + r[j].y * vv.y + r[j].z * vv.z + r[j].w * vv.w;
        }
    }
    return s;
}

__device__ __forceinline__ float warp_sum(float s) {
    #pragma unroll
    for (int o = 16; o; o >>= 1) s += __shfl_xor_sync(0xFFFFFFFFu, s, o);
    return s;
}

// ---------------- block reduction helpers ----------------
__device__ __forceinline__ float block_reduce_max(float v, float* sm) {
    int lane = threadIdx.x & 31, wid = threadIdx.x >> 5;
    int nwarp = blockDim.x >> 5;
    #pragma unroll
    for (int o = 16; o; o >>= 1) v = fmaxf(v, __shfl_xor_sync(0xFFFFFFFFu, v, o));
    if (lane == 0) sm[wid] = v;
    __syncthreads();
    float r = (threadIdx.x < nwarp) ? sm[threadIdx.x] : -1e30f;
    if (wid == 0) {
        #pragma unroll
        for (int o = 16; o; o >>= 1) r = fmaxf(r, __shfl_xor_sync(0xFFFFFFFFu, r, o));
        if (lane == 0) sm[0] = r;
    }
    __syncthreads();
    float m = sm[0];
    __syncthreads();
    return m;
}

__device__ __forceinline__ float block_reduce_sum(float v, float* sm) {
    int lane = threadIdx.x & 31, wid = threadIdx.x >> 5;
    int nwarp = blockDim.x >> 5;
    #pragma unroll
    for (int o = 16; o; o >>= 1) v += __shfl_xor_sync(0xFFFFFFFFu, v, o);
    if (lane == 0) sm[wid] = v;
    __syncthreads();
    float r = (threadIdx.x < nwarp) ? sm[threadIdx.x] : 0.0f;
    if (wid == 0) {
        #pragma unroll
        for (int o = 16; o; o >>= 1) r += __shfl_xor_sync(0xFFFFFFFFu, r, o);
        if (lane == 0) sm[0] = r;
    }
    __syncthreads();
    float s = sm[0];
    __syncthreads();
    return s;
}

// ---------------- K1: attn logits (S=2) + W_hh@h gate base + scratch zeroing
// blocks [0, 1024): attn logits, warp = (row, seg)  -> g_log0/g_log1 plain writes
// blocks [1024, 3072): hh gates, warp-per-row       -> g_gates base (+b_hh+b_ih)
// blocks [0, 32) additionally zero g_lstm_in / g_attn_applied.
#define NA_BLOCKS 1024
__global__ __launch_bounds__(256) void phase1_kernel(
    const float* __restrict__ W_attn, const float* __restrict__ b_attn,
    const float* __restrict__ h0, const float* __restrict__ x0,
    const float* __restrict__ W_hh, const float* __restrict__ b_hh,
    const float* __restrict__ b_ih)
{
    int wid = threadIdx.x >> 5, lane = threadIdx.x & 31;
    if (blockIdx.x < 16) g_lstm_in[blockIdx.x * 256 + threadIdx.x] = 0.0f;
    else if (blockIdx.x < 32) g_attn_applied[(blockIdx.x - 16) * 256 + threadIdx.x] = 0.0f;

    if (blockIdx.x < NA_BLOCKS) {
        int w = blockIdx.x * 8 + wid;
        int row = w >> 1, seg = w & 1;
        const float4* a = (const float4*)(W_attn + (size_t)row * 2 * HD);
        const float4* b = a + HD / 4;
        int i0 = seg * (HD / 8);           // 512 float4s per segment
        float s = dot_seg(a, (const float4*)h0, i0, HD / 8, lane)
                + dot_seg(b, (const float4*)x0, i0, HD / 8, lane);
        s = warp_sum(s);
        if (lane == 0) {
            if (seg == 0) g_log0[row] = s + b_attn[row];
            else          g_log1[row] = s;
        }
    } else {
        int row = (blockIdx.x - NA_BLOCKS) * 8 + wid;   // [0, 4H)
        const float4* a = (const float4*)(W_hh + (size_t)row * HD);
        float s = dot_seg(a, (const float4*)h0, 0, HD / 4, lane);
        s = warp_sum(s);
        if (lane == 0) g_gates[row] = s + b_hh[row] + b_ih[row];
    }
}

// ---------------- K2: per-block online LSE + attn_applied slice -------------
// grid (4, 256) x 256 threads. Each block computes the full LSE over L=4096
// (single online pass over L2-resident logits), then accumulates its 16-row
// slice of attn_applied[c] = sum_l (logit[l]-lse)*enc[l,c] via atomicAdd.
__global__ __launch_bounds__(256) void attn_applied_kernel(const float* __restrict__ enc) {
    __shared__ float smm[32], sms[32];
    __shared__ float wsh[16];
    int t = threadIdx.x;
    int lane = t & 31, wid = t >> 5;

    // online (max, sum) over logits, 16 elems per thread
    float m = -1e30f, s = 0.0f;
    for (int i = t; i < LD; i += 256) {
        float v = g_log0[i] + g_log1[i];
        if (v > m) { s = s * expf(m - v) + 1.0f; m = v; }
        else        s += expf(v - m);
    }
    // warp pair-reduce
    #pragma unroll
    for (int o = 16; o; o >>= 1) {
        float m2 = __shfl_xor_sync(0xFFFFFFFFu, m, o);
        float s2 = __shfl_xor_sync(0xFFFFFFFFu, s, o);
        float M = fmaxf(m, m2);
        s = s * expf(m - M) + s2 * expf(m2 - M);
        m = M;
    }
    if (lane == 0) { smm[wid] = m; sms[wid] = s; }
    __syncthreads();
    if (wid == 0) {
        float mm = (lane < 8) ? smm[lane] : -1e30f;
        float ss = (lane < 8) ? sms[lane] : 0.0f;
        #pragma unroll
        for (int o = 4; o; o >>= 1) {
            float m2 = __shfl_xor_sync(0xFFFFFFFFu, mm, o);
            float s2 = __shfl_xor_sync(0xFFFFFFFFu, ss, o);
            float M = fmaxf(mm, m2);
            ss = ss * expf(mm - M) + s2 * expf(m2 - M);
            mm = M;
        }
        if (lane == 0) { smm[0] = mm; sms[0] = ss; }
    }
    __syncthreads();
    float lse = smm[0] + logf(sms[0]);

    int l0 = blockIdx.y * 16;
    if (t < 16) wsh[t] = g_log0[l0 + t] + g_log1[l0 + t] - lse;
    __syncthreads();

    int c4 = blockIdx.x * 256 + t;                   // float4 column [0,1024)
    const float4* e = (const float4*)enc;
    float4 acc = make_float4(0.f, 0.f, 0.f, 0.f);
    #pragma unroll
    for (int j = 0; j < 16; ++j) {
        float w = wsh[j];
        float4 ev = e[(size_t)(l0 + j) * (HD / 4) + c4];
        acc.x += w * ev.x; acc.y += w * ev.y;
        acc.z += w * ev.z; acc.w += w * ev.w;
    }
    atomicAdd(&g_attn_applied[c4 * 4 + 0], acc.x);
    atomicAdd(&g_attn_applied[c4 * 4 + 1], acc.y);
    atomicAdd(&g_attn_applied[c4 * 4 + 2], acc.z);
    atomicAdd(&g_attn_applied[c4 * 4 + 3], acc.w);
}

// ---------------- K3: lstm_in += [x, attn_applied] @ W_comb^T + b  (S=2) ----
__global__ __launch_bounds__(256) void comb_kernel(
    const float* __restrict__ W_comb, const float* __restrict__ b_comb,
    const float* __restrict__ x0)
{
    int wid = threadIdx.x >> 5, lane = threadIdx.x & 31;
    int w = blockIdx.x * 8 + wid;          // grid 1024
    int row = w >> 1, seg = w & 1;
    const float4* a = (const float4*)(W_comb + (size_t)row * 2 * HD);
    const float4* b = a + HD / 4;
    int i0 = seg * (HD / 8);
    float s = dot_seg(a, (const float4*)x0, i0, HD / 8, lane)
            + dot_seg(b, (const float4*)g_attn_applied, i0, HD / 8, lane);
    s = warp_sum(s);
    if (lane == 0)
        atomicAdd(&g_lstm_in[row], s + (seg == 0 ? b_comb[row] : 0.0f));
}

// ---------------- K4: gates += W_ih @ lstm_in  (S=2, bias already folded) ---
__global__ __launch_bounds__(256) void ih_kernel(const float* __restrict__ W_ih)
{
    int wid = threadIdx.x >> 5, lane = threadIdx.x & 31;
    int w = blockIdx.x * 8 + wid;          // grid 4096 -> (row, seg), rows [0,4H)
    int row = w >> 1, seg = w & 1;
    const float4* a = (const float4*)(W_ih + (size_t)row * HD);
    int i0 = seg * (HD / 8);
    float s = dot_seg(a, (const float4*)g_lstm_in, i0, HD / 8, lane);
    s = warp_sum(s);
    if (lane == 0) atomicAdd(&g_gates[row], s);
}

// ---------------- K5: LSTM cell elementwise ----------------
__global__ void lstm_kernel(const float* __restrict__ c0) {
    int i = blockIdx.x * blockDim.x + threadIdx.x;
    if (i >= HD) return;
    float ig = g_gates[i];
    float fg = g_gates[i + HD];
    float gg = g_gates[i + 2 * HD];
    float og = g_gates[i + 3 * HD];
    float si = 1.0f / (1.0f + expf(-ig));
    float sf = 1.0f / (1.0f + expf(-fg));
    float so = 1.0f / (1.0f + expf(-og));
    float cn = sf * c0[i] + si * tanhf(gg);
    g_hnew[i] = so * tanhf(cn);
}

// ---------------- K6: word = h_new @ W_out^T + b_out  (2.1 GB) --------------
__global__ __launch_bounds__(256) void wout_kernel(
    const float* __restrict__ W_out, const float* __restrict__ b_out)
{
    int wid = threadIdx.x >> 5, lane = threadIdx.x & 31;
    int row = blockIdx.x * 8 + wid;        // grid 16000
    const float4* a = (const float4*)(W_out + (size_t)row * HD);
    float s = dot_seg(a, (const float4*)g_hnew, 0, HD / 4, lane);
    s = warp_sum(s);
    if (lane == 0) g_word[row] = s + b_out[row];
}

// ---------------- K7: vocab logsumexp stage A ----------------
__global__ void word_lse_partial_kernel() {
    __shared__ float sm[32];
    int idx = blockIdx.x * blockDim.x + threadIdx.x;
    float x = g_word[idx];                 // V divisible by 256
    float M = block_reduce_max(x, sm);
    float S = block_reduce_sum(expf(x - M), sm);
    if (threadIdx.x == 0) { g_pmax[blockIdx.x] = M; g_psum[blockIdx.x] = S; }
}

// ---------------- K8: vocab logsumexp stage B ----------------
__global__ void word_lse_final_kernel(int nparts) {
    __shared__ float sm[32];
    int t = threadIdx.x;
    float m = (t < nparts) ? g_pmax[t] : -1e30f;
    float M = block_reduce_max(m, sm);
    float s = (t < nparts) ? g_psum[t] * expf(g_pmax[t] - M) : 0.0f;
    float S = block_reduce_sum(s, sm);
    if (t == 0) g_lse_word = M + logf(S);
}

// ---------------- K9: out = word - lse ----------------
__global__ void final_kernel(float* __restrict__ out) {
    int i = blockIdx.x * blockDim.x + threadIdx.x;
    if (i < VD) out[i] = g_word[i] - g_lse_word;
}

// ======================================================================
extern "C" void kernel_launch(void* const* d_in, const int* in_sizes, int n_in,
                              void* d_out, int out_size) {
    const float* enc    = (const float*)d_in[0];
    const float* h0     = (const float*)d_in[1];
    const float* c0     = (const float*)d_in[2];
    const float* x0     = (const float*)d_in[3];
    const float* W_attn = (const float*)d_in[4];
    const float* b_attn = (const float*)d_in[5];
    const float* W_comb = (const float*)d_in[6];
    const float* b_comb = (const float*)d_in[7];
    const float* W_ih   = (const float*)d_in[8];
    const float* b_ih   = (const float*)d_in[9];
    const float* W_hh   = (const float*)d_in[10];
    const float* b_hh   = (const float*)d_in[11];
    const float* W_out  = (const float*)d_in[12];
    const float* b_out  = (const float*)d_in[13];
    float* out = (float*)d_out;

    const int TPB = 256;

    // K1: attn logits (S=2) + W_hh@h gate base (+biases) + scratch zeroing
    phase1_kernel<<<NA_BLOCKS + (4 * HD) / 8, TPB>>>(W_attn, b_attn, h0, x0,
                                                     W_hh, b_hh, b_ih);
    // K2: per-block LSE + attn_applied   (64 MB, 1024 blocks)
    attn_applied_kernel<<<dim3(HD / 4 / TPB, 256), TPB>>>(enc);
    // K3: lstm_in = [x, attn_applied] @ W_comb^T + b   (S=2, 1024 blocks)
    comb_kernel<<<(2 * HD) / 8, TPB>>>(W_comb, b_comb, x0);
    // K4: gates += W_ih @ lstm_in   (S=2, 4096 blocks)
    ih_kernel<<<(2 * 4 * HD) / 8, TPB>>>(W_ih);
    // K5: LSTM cell
    lstm_kernel<<<HD / TPB, TPB>>>(c0);
    // K6: word = h_new @ W_out^T + b_out   (2.1 GB, 16000 blocks)
    wout_kernel<<<VD / 8, TPB>>>(W_out, b_out);
    // K7-8: logsumexp over V
    word_lse_partial_kernel<<<VD / TPB, TPB>>>();
    word_lse_final_kernel<<<1, 512>>>(VD / TPB);
    // K9: out = word - lse
    final_kernel<<<VD / TPB, TPB>>>(out);
}

// round 6
// speedup vs baseline: 1.0219x; 1.0134x over previous
#include <cuda_runtime.h>
#include <math.h>

#define HD 4096
#define LD 4096
#define VD 128000

// ---------------- scratch (device globals; no allocations) ----------------
__device__ __align__(16) float g_log0[LD];         // attn logits partial seg0 (+bias)
__device__ __align__(16) float g_log1[LD];         // attn logits partial seg1
__device__ __align__(16) float g_attn_applied[HD]; // zeroed by phase1, atomics in K2
__device__ __align__(16) float g_lstm_in[HD];      // zeroed by phase1, atomics in K3
__device__ __align__(16) float g_gates[4 * HD];    // base by phase1, atomics in K4
__device__ __align__(16) float g_hnew[HD];
__device__ __align__(16) float g_word[VD];
__device__ float g_pmax[VD / 256];
__device__ float g_psum[VD / 256];
__device__ float g_lse_word;

// ---------------- 8-deep front-batched single-row dot (streaming weights) ---
__device__ __forceinline__ float dot_seg(const float4* __restrict__ a,
                                         const float4* __restrict__ v,
                                         int i0, int n4, int lane)
{
    float s = 0.0f;
    for (int base = i0 + lane; base < i0 + n4; base += 256) {
        float4 r[8];
        #pragma unroll
        for (int j = 0; j < 8; ++j) r[j] = __ldcs(a + base + j * 32);
        #pragma unroll
        for (int j = 0; j < 8; ++j) {
            float4 vv = v[base + j * 32];
            s += r[j].x * vv.x + r[j].y * vv.y + r[j].z * vv.z + r[j].w * vv.w;
        }
    }
    return s;
}

// ---------------- dual-row dot: 8 weight loads per batch, vector loaded once
__device__ __forceinline__ void dot2_seg(const float4* __restrict__ a0,
                                         const float4* __restrict__ a1,
                                         const float4* __restrict__ v,
                                         int i0, int n4, int lane,
                                         float& out0, float& out1)
{
    float s0 = 0.0f, s1 = 0.0f;
    for (int base = i0 + lane; base < i0 + n4; base += 128) {
        float4 r0[4], r1[4];
        #pragma unroll
        for (int j = 0; j < 4; ++j) r0[j] = __ldcs(a0 + base + j * 32);
        #pragma unroll
        for (int j = 0; j < 4; ++j) r1[j] = __ldcs(a1 + base + j * 32);
        #pragma unroll
        for (int j = 0; j < 4; ++j) {
            float4 vv = v[base + j * 32];
            s0 += r0[j].x * vv.x + r0[j].y * vv.y + r0[j].z * vv.z + r0[j].w * vv.w;
            s1 += r1[j].x * vv.x + r1[j].y * vv.y + r1[j].z * vv.z + r1[j].w * vv.w;
        }
    }
    out0 = s0; out1 = s1;
}

__device__ __forceinline__ float warp_sum(float s) {
    #pragma unroll
    for (int o = 16; o; o >>= 1) s += __shfl_xor_sync(0xFFFFFFFFu, s, o);
    return s;
}

// ---------------- block reduction helpers ----------------
__device__ __forceinline__ float block_reduce_max(float v, float* sm) {
    int lane = threadIdx.x & 31, wid = threadIdx.x >> 5;
    int nwarp = blockDim.x >> 5;
    #pragma unroll
    for (int o = 16; o; o >>= 1) v = fmaxf(v, __shfl_xor_sync(0xFFFFFFFFu, v, o));
    if (lane == 0) sm[wid] = v;
    __syncthreads();
    float r = (threadIdx.x < nwarp) ? sm[threadIdx.x] : -1e30f;
    if (wid == 0) {
        #pragma unroll
        for (int o = 16; o; o >>= 1) r = fmaxf(r, __shfl_xor_sync(0xFFFFFFFFu, r, o));
        if (lane == 0) sm[0] = r;
    }
    __syncthreads();
    float m = sm[0];
    __syncthreads();
    return m;
}

__device__ __forceinline__ float block_reduce_sum(float v, float* sm) {
    int lane = threadIdx.x & 31, wid = threadIdx.x >> 5;
    int nwarp = blockDim.x >> 5;
    #pragma unroll
    for (int o = 16; o; o >>= 1) v += __shfl_xor_sync(0xFFFFFFFFu, v, o);
    if (lane == 0) sm[wid] = v;
    __syncthreads();
    float r = (threadIdx.x < nwarp) ? sm[threadIdx.x] : 0.0f;
    if (wid == 0) {
        #pragma unroll
        for (int o = 16; o; o >>= 1) r += __shfl_xor_sync(0xFFFFFFFFu, r, o);
        if (lane == 0) sm[0] = r;
    }
    __syncthreads();
    float s = sm[0];
    __syncthreads();
    return s;
}

// ---------------- K1: attn logits (S=2) + W_hh@h gate base + scratch zeroing
#define NA_BLOCKS 1024
__global__ __launch_bounds__(256) void phase1_kernel(
    const float* __restrict__ W_attn, const float* __restrict__ b_attn,
    const float* __restrict__ h0, const float* __restrict__ x0,
    const float* __restrict__ W_hh, const float* __restrict__ b_hh,
    const float* __restrict__ b_ih)
{
    int wid = threadIdx.x >> 5, lane = threadIdx.x & 31;
    if (blockIdx.x < 16) g_lstm_in[blockIdx.x * 256 + threadIdx.x] = 0.0f;
    else if (blockIdx.x < 32) g_attn_applied[(blockIdx.x - 16) * 256 + threadIdx.x] = 0.0f;

    if (blockIdx.x < NA_BLOCKS) {
        int w = blockIdx.x * 8 + wid;
        int row = w >> 1, seg = w & 1;
        const float4* a = (const float4*)(W_attn + (size_t)row * 2 * HD);
        const float4* b = a + HD / 4;
        int i0 = seg * (HD / 8);           // 512 float4s per segment
        float s = dot_seg(a, (const float4*)h0, i0, HD / 8, lane)
                + dot_seg(b, (const float4*)x0, i0, HD / 8, lane);
        s = warp_sum(s);
        if (lane == 0) {
            if (seg == 0) g_log0[row] = s + b_attn[row];
            else          g_log1[row] = s;
        }
    } else {
        int w = (blockIdx.x - NA_BLOCKS) * 8 + wid;     // [0, 2H): row pairs
        int row = w * 2;
        const float4* a0 = (const float4*)(W_hh + (size_t)row * HD);
        const float4* a1 = a0 + HD / 4;
        float s0, s1;
        dot2_seg(a0, a1, (const float4*)h0, 0, HD / 4, lane, s0, s1);
        s0 = warp_sum(s0); s1 = warp_sum(s1);
        if (lane == 0) {
            g_gates[row]     = s0 + b_hh[row]     + b_ih[row];
            g_gates[row + 1] = s1 + b_hh[row + 1] + b_ih[row + 1];
        }
    }
}

// ---------------- K2: per-block online LSE + attn_applied slice -------------
__global__ __launch_bounds__(256) void attn_applied_kernel(const float* __restrict__ enc) {
    __shared__ float smm[32], sms[32];
    __shared__ float wsh[16];
    int t = threadIdx.x;
    int lane = t & 31, wid = t >> 5;

    float m = -1e30f, s = 0.0f;
    for (int i = t; i < LD; i += 256) {
        float v = g_log0[i] + g_log1[i];
        if (v > m) { s = s * expf(m - v) + 1.0f; m = v; }
        else        s += expf(v - m);
    }
    #pragma unroll
    for (int o = 16; o; o >>= 1) {
        float m2 = __shfl_xor_sync(0xFFFFFFFFu, m, o);
        float s2 = __shfl_xor_sync(0xFFFFFFFFu, s, o);
        float M = fmaxf(m, m2);
        s = s * expf(m - M) + s2 * expf(m2 - M);
        m = M;
    }
    if (lane == 0) { smm[wid] = m; sms[wid] = s; }
    __syncthreads();
    if (wid == 0) {
        float mm = (lane < 8) ? smm[lane] : -1e30f;
        float ss = (lane < 8) ? sms[lane] : 0.0f;
        #pragma unroll
        for (int o = 4; o; o >>= 1) {
            float m2 = __shfl_xor_sync(0xFFFFFFFFu, mm, o);
            float s2 = __shfl_xor_sync(0xFFFFFFFFu, ss, o);
            float M = fmaxf(mm, m2);
            ss = ss * expf(mm - M) + s2 * expf(m2 - M);
            mm = M;
        }
        if (lane == 0) { smm[0] = mm; sms[0] = ss; }
    }
    __syncthreads();
    float lse = smm[0] + logf(sms[0]);

    int l0 = blockIdx.y * 16;
    if (t < 16) wsh[t] = g_log0[l0 + t] + g_log1[l0 + t] - lse;
    __syncthreads();

    int c4 = blockIdx.x * 256 + t;                   // float4 column [0,1024)
    const float4* e = (const float4*)enc;
    float4 acc = make_float4(0.f, 0.f, 0.f, 0.f);
    #pragma unroll
    for (int j = 0; j < 16; ++j) {
        float w = wsh[j];
        float4 ev = __ldcs(e + (size_t)(l0 + j) * (HD / 4) + c4);
        acc.x += w * ev.x; acc.y += w * ev.y;
        acc.z += w * ev.z; acc.w += w * ev.w;
    }
    atomicAdd(&g_attn_applied[c4 * 4 + 0], acc.x);
    atomicAdd(&g_attn_applied[c4 * 4 + 1], acc.y);
    atomicAdd(&g_attn_applied[c4 * 4 + 2], acc.z);
    atomicAdd(&g_attn_applied[c4 * 4 + 3], acc.w);
}

// ---------------- K3: lstm_in += [x, attn_applied] @ W_comb^T + b  (S=2) ----
__global__ __launch_bounds__(256) void comb_kernel(
    const float* __restrict__ W_comb, const float* __restrict__ b_comb,
    const float* __restrict__ x0)
{
    int wid = threadIdx.x >> 5, lane = threadIdx.x & 31;
    int w = blockIdx.x * 8 + wid;          // grid 1024
    int row = w >> 1, seg = w & 1;
    const float4* a = (const float4*)(W_comb + (size_t)row * 2 * HD);
    const float4* b = a + HD / 4;
    int i0 = seg * (HD / 8);
    float s = dot_seg(a, (const float4*)x0, i0, HD / 8, lane)
            + dot_seg(b, (const float4*)g_attn_applied, i0, HD / 8, lane);
    s = warp_sum(s);
    if (lane == 0)
        atomicAdd(&g_lstm_in[row], s + (seg == 0 ? b_comb[row] : 0.0f));
}

// ---------------- K4: gates += W_ih @ lstm_in  (2 rows/warp, S=2) -----------
__global__ __launch_bounds__(256) void ih_kernel(const float* __restrict__ W_ih)
{
    int wid = threadIdx.x >> 5, lane = threadIdx.x & 31;
    int w = blockIdx.x * 8 + wid;          // grid 2048 -> (pair, seg)
    int pair = w >> 1, seg = w & 1;
    int row = pair * 2;
    const float4* a0 = (const float4*)(W_ih + (size_t)row * HD);
    const float4* a1 = a0 + HD / 4;
    int i0 = seg * (HD / 8);
    float s0, s1;
    dot2_seg(a0, a1, (const float4*)g_lstm_in, i0, HD / 8, lane, s0, s1);
    s0 = warp_sum(s0); s1 = warp_sum(s1);
    if (lane == 0) {
        atomicAdd(&g_gates[row],     s0);
        atomicAdd(&g_gates[row + 1], s1);
    }
}

// ---------------- K5: LSTM cell elementwise ----------------
__global__ void lstm_kernel(const float* __restrict__ c0) {
    int i = blockIdx.x * blockDim.x + threadIdx.x;
    if (i >= HD) return;
    float ig = g_gates[i];
    float fg = g_gates[i + HD];
    float gg = g_gates[i + 2 * HD];
    float og = g_gates[i + 3 * HD];
    float si = 1.0f / (1.0f + expf(-ig));
    float sf = 1.0f / (1.0f + expf(-fg));
    float so = 1.0f / (1.0f + expf(-og));
    float cn = sf * c0[i] + si * tanhf(gg);
    g_hnew[i] = so * tanhf(cn);
}

// ---------------- K6: word = h_new @ W_out^T + b_out  (2 rows/warp) ---------
__global__ __launch_bounds__(256) void wout_kernel(
    const float* __restrict__ W_out, const float* __restrict__ b_out)
{
    int wid = threadIdx.x >> 5, lane = threadIdx.x & 31;
    int w = blockIdx.x * 8 + wid;          // grid 8000 -> 64000 warps
    int row = w * 2;
    const float4* a0 = (const float4*)(W_out + (size_t)row * HD);
    const float4* a1 = a0 + HD / 4;
    float s0, s1;
    dot2_seg(a0, a1, (const float4*)g_hnew, 0, HD / 4, lane, s0, s1);
    s0 = warp_sum(s0); s1 = warp_sum(s1);
    if (lane == 0) {
        g_word[row]     = s0 + b_out[row];
        g_word[row + 1] = s1 + b_out[row + 1];
    }
}

// ---------------- K7: vocab logsumexp stage A ----------------
__global__ void word_lse_partial_kernel() {
    __shared__ float sm[32];
    int idx = blockIdx.x * blockDim.x + threadIdx.x;
    float x = g_word[idx];                 // V divisible by 256
    float M = block_reduce_max(x, sm);
    float S = block_reduce_sum(expf(x - M), sm);
    if (threadIdx.x == 0) { g_pmax[blockIdx.x] = M; g_psum[blockIdx.x] = S; }
}

// ---------------- K8: vocab logsumexp stage B ----------------
__global__ void word_lse_final_kernel(int nparts) {
    __shared__ float sm[32];
    int t = threadIdx.x;
    float m = (t < nparts) ? g_pmax[t] : -1e30f;
    float M = block_reduce_max(m, sm);
    float s = (t < nparts) ? g_psum[t] * expf(g_pmax[t] - M) : 0.0f;
    float S = block_reduce_sum(s, sm);
    if (t == 0) g_lse_word = M + logf(S);
}

// ---------------- K9: out = word - lse ----------------
__global__ void final_kernel(float* __restrict__ out) {
    int i = blockIdx.x * blockDim.x + threadIdx.x;
    if (i < VD) out[i] = g_word[i] - g_lse_word;
}

// ======================================================================
extern "C" void kernel_launch(void* const* d_in, const int* in_sizes, int n_in,
                              void* d_out, int out_size) {
    const float* enc    = (const float*)d_in[0];
    const float* h0     = (const float*)d_in[1];
    const float* c0     = (const float*)d_in[2];
    const float* x0     = (const float*)d_in[3];
    const float* W_attn = (const float*)d_in[4];
    const float* b_attn = (const float*)d_in[5];
    const float* W_comb = (const float*)d_in[6];
    const float* b_comb = (const float*)d_in[7];
    const float* W_ih   = (const float*)d_in[8];
    const float* b_ih   = (const float*)d_in[9];
    const float* W_hh   = (const float*)d_in[10];
    const float* b_hh   = (const float*)d_in[11];
    const float* W_out  = (const float*)d_in[12];
    const float* b_out  = (const float*)d_in[13];
    float* out = (float*)d_out;

    const int TPB = 256;

    // K1: attn logits (S=2, 1024 blks) + W_hh@h base (2 rows/warp, 1024 blks)
    phase1_kernel<<<NA_BLOCKS + (2 * HD) / 8, TPB>>>(W_attn, b_attn, h0, x0,
                                                     W_hh, b_hh, b_ih);
    // K2: per-block LSE + attn_applied   (64 MB, 1024 blocks)
    attn_applied_kernel<<<dim3(HD / 4 / TPB, 256), TPB>>>(enc);
    // K3: lstm_in = [x, attn_applied] @ W_comb^T + b   (S=2, 1024 blocks)
    comb_kernel<<<(2 * HD) / 8, TPB>>>(W_comb, b_comb, x0);
    // K4: gates += W_ih @ lstm_in   (2 rows/warp, S=2, 2048 blocks)
    ih_kernel<<<(4 * HD) / 8, TPB>>>(W_ih);
    // K5: LSTM cell
    lstm_kernel<<<HD / TPB, TPB>>>(c0);
    // K6: word = h_new @ W_out^T + b_out   (2.1 GB, 2 rows/warp, 8000 blocks)
    wout_kernel<<<VD / 16, TPB>>>(W_out, b_out);
    // K7-8: logsumexp over V
    word_lse_partial_kernel<<<VD / TPB, TPB>>>();
    word_lse_final_kernel<<<1, 512>>>(VD / TPB);
    // K9: out = word - lse
    final_kernel<<<VD / TPB, TPB>>>(out);
}

// round 7
// speedup vs baseline: 1.0562x; 1.0336x over previous
#include <cuda_runtime.h>
#include <math.h>

#define HD 4096
#define LD 4096
#define VD 128000

// ---------------- scratch (device globals; no allocations) ----------------
__device__ __align__(16) float g_log0[LD];         // attn logits partial seg0 (+bias)
__device__ __align__(16) float g_log1[LD];         // attn logits partial seg1
__device__ __align__(16) float g_attn_applied[HD]; // zeroed by phase1, atomics in K2
__device__ __align__(16) float g_lstm_in[HD];      // zeroed by phase1, atomics in K3
__device__ __align__(16) float g_gates[4 * HD];    // base by phase1, atomics in K4
__device__ __align__(16) float g_hnew[HD];
__device__ __align__(16) float g_word[VD];
__device__ float g_pmax[VD / 256];
__device__ float g_psum[VD / 256];
__device__ float g_lse_word;

// ---------------- 8-deep front-batched single-row dot (streaming weights) ---
__device__ __forceinline__ float dot_seg(const float4* __restrict__ a,
                                         const float4* __restrict__ v,
                                         int i0, int n4, int lane)
{
    float s = 0.0f;
    for (int base = i0 + lane; base < i0 + n4; base += 256) {
        float4 r[8];
        #pragma unroll
        for (int j = 0; j < 8; ++j) r[j] = __ldcs(a + base + j * 32);
        #pragma unroll
        for (int j = 0; j < 8; ++j) {
            float4 vv = v[base + j * 32];
            s += r[j].x * vv.x + r[j].y * vv.y + r[j].z * vv.z + r[j].w * vv.w;
        }
    }
    return s;
}

__device__ __forceinline__ float warp_sum(float s) {
    #pragma unroll
    for (int o = 16; o; o >>= 1) s += __shfl_xor_sync(0xFFFFFFFFu, s, o);
    return s;
}

// ---------------- block reduction helpers ----------------
__device__ __forceinline__ float block_reduce_max(float v, float* sm) {
    int lane = threadIdx.x & 31, wid = threadIdx.x >> 5;
    int nwarp = blockDim.x >> 5;
    #pragma unroll
    for (int o = 16; o; o >>= 1) v = fmaxf(v, __shfl_xor_sync(0xFFFFFFFFu, v, o));
    if (lane == 0) sm[wid] = v;
    __syncthreads();
    float r = (threadIdx.x < nwarp) ? sm[threadIdx.x] : -1e30f;
    if (wid == 0) {
        #pragma unroll
        for (int o = 16; o; o >>= 1) r = fmaxf(r, __shfl_xor_sync(0xFFFFFFFFu, r, o));
        if (lane == 0) sm[0] = r;
    }
    __syncthreads();
    float m = sm[0];
    __syncthreads();
    return m;
}

__device__ __forceinline__ float block_reduce_sum(float v, float* sm) {
    int lane = threadIdx.x & 31, wid = threadIdx.x >> 5;
    int nwarp = blockDim.x >> 5;
    #pragma unroll
    for (int o = 16; o; o >>= 1) v += __shfl_xor_sync(0xFFFFFFFFu, v, o);
    if (lane == 0) sm[wid] = v;
    __syncthreads();
    float r = (threadIdx.x < nwarp) ? sm[threadIdx.x] : 0.0f;
    if (wid == 0) {
        #pragma unroll
        for (int o = 16; o; o >>= 1) r += __shfl_xor_sync(0xFFFFFFFFu, r, o);
        if (lane == 0) sm[0] = r;
    }
    __syncthreads();
    float s = sm[0];
    __syncthreads();
    return s;
}

// ---------------- K1: attn logits (S=2) + W_hh@h gate base + scratch zeroing
// blocks [0, 1024): attn logits, warp = (row, seg)  -> g_log0/g_log1
// blocks [1024, 3072): hh gates, warp-per-row 8-deep -> g_gates (+b_hh+b_ih)
#define NA_BLOCKS 1024
__global__ __launch_bounds__(256) void phase1_kernel(
    const float* __restrict__ W_attn, const float* __restrict__ b_attn,
    const float* __restrict__ h0, const float* __restrict__ x0,
    const float* __restrict__ W_hh, const float* __restrict__ b_hh,
    const float* __restrict__ b_ih)
{
    int wid = threadIdx.x >> 5, lane = threadIdx.x & 31;
    if (blockIdx.x < 16) g_lstm_in[blockIdx.x * 256 + threadIdx.x] = 0.0f;
    else if (blockIdx.x < 32) g_attn_applied[(blockIdx.x - 16) * 256 + threadIdx.x] = 0.0f;

    if (blockIdx.x < NA_BLOCKS) {
        int w = blockIdx.x * 8 + wid;
        int row = w >> 1, seg = w & 1;
        const float4* a = (const float4*)(W_attn + (size_t)row * 2 * HD);
        const float4* b = a + HD / 4;
        int i0 = seg * (HD / 8);           // 512 float4s per segment
        float s = dot_seg(a, (const float4*)h0, i0, HD / 8, lane)
                + dot_seg(b, (const float4*)x0, i0, HD / 8, lane);
        s = warp_sum(s);
        if (lane == 0) {
            if (seg == 0) g_log0[row] = s + b_attn[row];
            else          g_log1[row] = s;
        }
    } else {
        int row = (blockIdx.x - NA_BLOCKS) * 8 + wid;   // [0, 4H)
        const float4* a = (const float4*)(W_hh + (size_t)row * HD);
        float s = dot_seg(a, (const float4*)h0, 0, HD / 4, lane);
        s = warp_sum(s);
        if (lane == 0) g_gates[row] = s + b_hh[row] + b_ih[row];
    }
}

// ---------------- K2: per-block online LSE + attn_applied slice -------------
__global__ __launch_bounds__(256) void attn_applied_kernel(const float* __restrict__ enc) {
    __shared__ float smm[32], sms[32];
    __shared__ float wsh[16];
    int t = threadIdx.x;
    int lane = t & 31, wid = t >> 5;

    float m = -1e30f, s = 0.0f;
    for (int i = t; i < LD; i += 256) {
        float v = g_log0[i] + g_log1[i];
        if (v > m) { s = s * expf(m - v) + 1.0f; m = v; }
        else        s += expf(v - m);
    }
    #pragma unroll
    for (int o = 16; o; o >>= 1) {
        float m2 = __shfl_xor_sync(0xFFFFFFFFu, m, o);
        float s2 = __shfl_xor_sync(0xFFFFFFFFu, s, o);
        float M = fmaxf(m, m2);
        s = s * expf(m - M) + s2 * expf(m2 - M);
        m = M;
    }
    if (lane == 0) { smm[wid] = m; sms[wid] = s; }
    __syncthreads();
    if (wid == 0) {
        float mm = (lane < 8) ? smm[lane] : -1e30f;
        float ss = (lane < 8) ? sms[lane] : 0.0f;
        #pragma unroll
        for (int o = 4; o; o >>= 1) {
            float m2 = __shfl_xor_sync(0xFFFFFFFFu, mm, o);
            float s2 = __shfl_xor_sync(0xFFFFFFFFu, ss, o);
            float M = fmaxf(mm, m2);
            ss = ss * expf(mm - M) + s2 * expf(m2 - M);
            mm = M;
        }
        if (lane == 0) { smm[0] = mm; sms[0] = ss; }
    }
    __syncthreads();
    float lse = smm[0] + logf(sms[0]);

    int l0 = blockIdx.y * 16;
    if (t < 16) wsh[t] = g_log0[l0 + t] + g_log1[l0 + t] - lse;
    __syncthreads();

    int c4 = blockIdx.x * 256 + t;                   // float4 column [0,1024)
    const float4* e = (const float4*)enc;
    float4 acc = make_float4(0.f, 0.f, 0.f, 0.f);
    #pragma unroll
    for (int j = 0; j < 16; ++j) {
        float w = wsh[j];
        float4 ev = __ldcs(e + (size_t)(l0 + j) * (HD / 4) + c4);
        acc.x += w * ev.x; acc.y += w * ev.y;
        acc.z += w * ev.z; acc.w += w * ev.w;
    }
    atomicAdd(&g_attn_applied[c4 * 4 + 0], acc.x);
    atomicAdd(&g_attn_applied[c4 * 4 + 1], acc.y);
    atomicAdd(&g_attn_applied[c4 * 4 + 2], acc.z);
    atomicAdd(&g_attn_applied[c4 * 4 + 3], acc.w);
}

// ---------------- K3: lstm_in += [x, attn_applied] @ W_comb^T + b  (S=2) ----
__global__ __launch_bounds__(256) void comb_kernel(
    const float* __restrict__ W_comb, const float* __restrict__ b_comb,
    const float* __restrict__ x0)
{
    int wid = threadIdx.x >> 5, lane = threadIdx.x & 31;
    int w = blockIdx.x * 8 + wid;          // grid 1024
    int row = w >> 1, seg = w & 1;
    const float4* a = (const float4*)(W_comb + (size_t)row * 2 * HD);
    const float4* b = a + HD / 4;
    int i0 = seg * (HD / 8);
    float s = dot_seg(a, (const float4*)x0, i0, HD / 8, lane)
            + dot_seg(b, (const float4*)g_attn_applied, i0, HD / 8, lane);
    s = warp_sum(s);
    if (lane == 0)
        atomicAdd(&g_lstm_in[row], s + (seg == 0 ? b_comb[row] : 0.0f));
}

// ---------------- K4: gates += W_ih @ lstm_in  (1 row/warp, S=2, 8-deep) ----
__global__ __launch_bounds__(256) void ih_kernel(const float* __restrict__ W_ih)
{
    int wid = threadIdx.x >> 5, lane = threadIdx.x & 31;
    int w = blockIdx.x * 8 + wid;          // grid 4096 -> (row, seg), rows [0,4H)
    int row = w >> 1, seg = w & 1;
    const float4* a = (const float4*)(W_ih + (size_t)row * HD);
    int i0 = seg * (HD / 8);
    float s = dot_seg(a, (const float4*)g_lstm_in, i0, HD / 8, lane);
    s = warp_sum(s);
    if (lane == 0) atomicAdd(&g_gates[row], s);
}

// ---------------- K5: LSTM cell elementwise ----------------
__global__ void lstm_kernel(const float* __restrict__ c0) {
    int i = blockIdx.x * blockDim.x + threadIdx.x;
    if (i >= HD) return;
    float ig = g_gates[i];
    float fg = g_gates[i + HD];
    float gg = g_gates[i + 2 * HD];
    float og = g_gates[i + 3 * HD];
    float si = 1.0f / (1.0f + expf(-ig));
    float sf = 1.0f / (1.0f + expf(-fg));
    float so = 1.0f / (1.0f + expf(-og));
    float cn = sf * c0[i] + si * tanhf(gg);
    g_hnew[i] = so * tanhf(cn);
}

// ---------------- K6: word = h_new @ W_out^T + b_out  (1 row/warp, 8-deep) --
__global__ __launch_bounds__(256) void wout_kernel(
    const float* __restrict__ W_out, const float* __restrict__ b_out)
{
    int wid = threadIdx.x >> 5, lane = threadIdx.x & 31;
    int row = blockIdx.x * 8 + wid;        // grid 16000
    const float4* a = (const float4*)(W_out + (size_t)row * HD);
    float s = dot_seg(a, (const float4*)g_hnew, 0, HD / 4, lane);
    s = warp_sum(s);
    if (lane == 0) g_word[row] = s + b_out[row];
}

// ---------------- K7: vocab logsumexp stage A ----------------
__global__ void word_lse_partial_kernel() {
    __shared__ float sm[32];
    int idx = blockIdx.x * blockDim.x + threadIdx.x;
    float x = g_word[idx];                 // V divisible by 256
    float M = block_reduce_max(x, sm);
    float S = block_reduce_sum(expf(x - M), sm);
    if (threadIdx.x == 0) { g_pmax[blockIdx.x] = M; g_psum[blockIdx.x] = S; }
}

// ---------------- K8: vocab logsumexp stage B ----------------
__global__ void word_lse_final_kernel(int nparts) {
    __shared__ float sm[32];
    int t = threadIdx.x;
    float m = (t < nparts) ? g_pmax[t] : -1e30f;
    float M = block_reduce_max(m, sm);
    float s = (t < nparts) ? g_psum[t] * expf(g_pmax[t] - M) : 0.0f;
    float S = block_reduce_sum(s, sm);
    if (t == 0) g_lse_word = M + logf(S);
}

// ---------------- K9: out = word - lse ----------------
__global__ void final_kernel(float* __restrict__ out) {
    int i = blockIdx.x * blockDim.x + threadIdx.x;
    if (i < VD) out[i] = g_word[i] - g_lse_word;
}

// ======================================================================
extern "C" void kernel_launch(void* const* d_in, const int* in_sizes, int n_in,
                              void* d_out, int out_size) {
    const float* enc    = (const float*)d_in[0];
    const float* h0     = (const float*)d_in[1];
    const float* c0     = (const float*)d_in[2];
    const float* x0     = (const float*)d_in[3];
    const float* W_attn = (const float*)d_in[4];
    const float* b_attn = (const float*)d_in[5];
    const float* W_comb = (const float*)d_in[6];
    const float* b_comb = (const float*)d_in[7];
    const float* W_ih   = (const float*)d_in[8];
    const float* b_ih   = (const float*)d_in[9];
    const float* W_hh   = (const float*)d_in[10];
    const float* b_hh   = (const float*)d_in[11];
    const float* W_out  = (const float*)d_in[12];
    const float* b_out  = (const float*)d_in[13];
    float* out = (float*)d_out;

    const int TPB = 256;

    // K1: attn logits (S=2, 1024 blks) + W_hh@h base (1 row/warp, 2048 blks)
    phase1_kernel<<<NA_BLOCKS + (4 * HD) / 8, TPB>>>(W_attn, b_attn, h0, x0,
                                                     W_hh, b_hh, b_ih);
    // K2: per-block LSE + attn_applied   (64 MB, 1024 blocks)
    attn_applied_kernel<<<dim3(HD / 4 / TPB, 256), TPB>>>(enc);
    // K3: lstm_in = [x, attn_applied] @ W_comb^T + b   (S=2, 1024 blocks)
    comb_kernel<<<(2 * HD) / 8, TPB>>>(W_comb, b_comb, x0);
    // K4: gates += W_ih @ lstm_in   (S=2, 4096 blocks)
    ih_kernel<<<(2 * 4 * HD) / 8, TPB>>>(W_ih);
    // K5: LSTM cell
    lstm_kernel<<<HD / TPB, TPB>>>(c0);
    // K6: word = h_new @ W_out^T + b_out   (2.1 GB, 16000 blocks)
    wout_kernel<<<VD / 8, TPB>>>(W_out, b_out);
    // K7-8: logsumexp over V
    word_lse_partial_kernel<<<VD / TPB, TPB>>>();
    word_lse_final_kernel<<<1, 512>>>(VD / TPB);
    // K9: out = word - lse
    final_kernel<<<VD / TPB, TPB>>>(out);
}